// round 6
// baseline (speedup 1.0000x reference)
#include <cuda_runtime.h>
#include <cuda_bf16.h>
#include <cstdint>

// DistMult decoder: out[e] = sigmoid( sum_d x[l,d] * R[t,d] * x[r,d] )
// E = 4M edges, D = 32 floats (row = 128B = one L2 line).
//
// R5 state: 66us, L1 64%, L2 58%, issue 47%, occ 55% (48 regs, 5 blk/SM).
// Nothing saturated -> still latency/issue mixed. R6: (a) 6 blocks/SM via
// 42-reg ceiling, (b) u32 offset addressing (kills IMAD.WIDE address pairs,
// frees regs + alu issue), (c) scalar edge_type probes instead of int4.

#define DIM 32

__global__ void __launch_bounds__(256, 6) distmult_kernel(
    const float* __restrict__ x,
    const float* __restrict__ R,
    const int* __restrict__ edge_index,  // [2, E] int32
    const int* __restrict__ edge_type,   // [E] int32
    float* __restrict__ out,
    int E)
{
    int tid = blockIdx.x * blockDim.x + threadIdx.x;
    int g = tid >> 3;           // 8-lane group; handles edges 4g..4g+3
    unsigned i = threadIdx.x & 7u;  // 16B chunk within a row
    int e0 = g * 4;
    if (e0 >= E) return;

    const float4* __restrict__ xv = reinterpret_cast<const float4*>(x);
    const float4* __restrict__ rv = reinterpret_cast<const float4*>(R);

    if (e0 + 3 < E) {
        int4 L  = reinterpret_cast<const int4*>(edge_index)[g];
        int4 Rt = reinterpret_cast<const int4*>(edge_index + E)[g];
        int t0 = edge_type[e0];
        int t3 = edge_type[e0 + 3];

        // u32 element offsets: node_id*8 + i < 2^20, fits 32-bit addressing
        float4 a0 = xv[(unsigned)L.x * 8u + i];
        float4 a1 = xv[(unsigned)L.y * 8u + i];
        float4 a2 = xv[(unsigned)L.z * 8u + i];
        float4 a3 = xv[(unsigned)L.w * 8u + i];
        float4 b0 = xv[(unsigned)Rt.x * 8u + i];
        float4 b1 = xv[(unsigned)Rt.y * 8u + i];
        float4 b2 = xv[(unsigned)Rt.z * 8u + i];
        float4 b3 = xv[(unsigned)Rt.w * 8u + i];

        float s0, s1, s2, s3;
        if (t0 == t3) {
            // sorted types: one shared R row (~99.9% of groups)
            float4 c = rv[(unsigned)t0 * 8u + i];
            s0 = a0.x * c.x * b0.x;
            s0 = fmaf(a0.y * c.y, b0.y, s0);
            s0 = fmaf(a0.z * c.z, b0.z, s0);
            s0 = fmaf(a0.w * c.w, b0.w, s0);
            s1 = a1.x * c.x * b1.x;
            s1 = fmaf(a1.y * c.y, b1.y, s1);
            s1 = fmaf(a1.z * c.z, b1.z, s1);
            s1 = fmaf(a1.w * c.w, b1.w, s1);
            s2 = a2.x * c.x * b2.x;
            s2 = fmaf(a2.y * c.y, b2.y, s2);
            s2 = fmaf(a2.z * c.z, b2.z, s2);
            s2 = fmaf(a2.w * c.w, b2.w, s2);
            s3 = a3.x * c.x * b3.x;
            s3 = fmaf(a3.y * c.y, b3.y, s3);
            s3 = fmaf(a3.z * c.z, b3.z, s3);
            s3 = fmaf(a3.w * c.w, b3.w, s3);
        } else {
            // relation boundary inside the group (rare)
            int t1 = edge_type[e0 + 1];
            int t2 = edge_type[e0 + 2];
            float4 c0 = rv[(unsigned)t0 * 8u + i];
            float4 c1 = rv[(unsigned)t1 * 8u + i];
            float4 c2 = rv[(unsigned)t2 * 8u + i];
            float4 c3 = rv[(unsigned)t3 * 8u + i];
            s0 = a0.x * c0.x * b0.x;
            s0 = fmaf(a0.y * c0.y, b0.y, s0);
            s0 = fmaf(a0.z * c0.z, b0.z, s0);
            s0 = fmaf(a0.w * c0.w, b0.w, s0);
            s1 = a1.x * c1.x * b1.x;
            s1 = fmaf(a1.y * c1.y, b1.y, s1);
            s1 = fmaf(a1.z * c1.z, b1.z, s1);
            s1 = fmaf(a1.w * c1.w, b1.w, s1);
            s2 = a2.x * c2.x * b2.x;
            s2 = fmaf(a2.y * c2.y, b2.y, s2);
            s2 = fmaf(a2.z * c2.z, b2.z, s2);
            s2 = fmaf(a2.w * c2.w, b2.w, s2);
            s3 = a3.x * c3.x * b3.x;
            s3 = fmaf(a3.y * c3.y, b3.y, s3);
            s3 = fmaf(a3.z * c3.z, b3.z, s3);
            s3 = fmaf(a3.w * c3.w, b3.w, s3);
        }

        // packed 8-lane reduction of 4 values: 7 SHFLs total
        s0 += __shfl_xor_sync(0xFFFFFFFFu, s0, 4);
        s1 += __shfl_xor_sync(0xFFFFFFFFu, s1, 4);
        s2 += __shfl_xor_sync(0xFFFFFFFFu, s2, 4);
        s3 += __shfl_xor_sync(0xFFFFFFFFu, s3, 4);
        bool b2sel = (i & 2u) != 0u;
        float keep01 = b2sel ? s1 : s0;
        float send01 = b2sel ? s0 : s1;
        keep01 += __shfl_xor_sync(0xFFFFFFFFu, send01, 2);
        float keep23 = b2sel ? s3 : s2;
        float send23 = b2sel ? s2 : s3;
        keep23 += __shfl_xor_sync(0xFFFFFFFFu, send23, 2);
        bool b1sel = (i & 1u) != 0u;
        float keep = b1sel ? keep23 : keep01;
        float send = b1sel ? keep01 : keep23;
        keep += __shfl_xor_sync(0xFFFFFFFFu, send, 1);
        // lane i in 0..3 holds edge e0 + ((i&1)<<1 | (i>>1))

        if (i < 4u) {
            int j = (int)(((i & 1u) << 1) | (i >> 1));
            out[e0 + j] = 1.0f / (1.0f + __expf(-keep));
        }
    } else {
        // scalar tail (unused when E % 4 == 0, kept for safety)
        for (int e = e0; e < E; e++) {
            int l = edge_index[e];
            int r = edge_index[E + e];
            int t = edge_type[e];
            float4 a = xv[(unsigned)l * 8u + i];
            float4 b = xv[(unsigned)r * 8u + i];
            float4 c = rv[(unsigned)t * 8u + i];
            float s = a.x * c.x * b.x;
            s = fmaf(a.y * c.y, b.y, s);
            s = fmaf(a.z * c.z, b.z, s);
            s = fmaf(a.w * c.w, b.w, s);
            s += __shfl_xor_sync(0xFFFFFFFFu, s, 1);
            s += __shfl_xor_sync(0xFFFFFFFFu, s, 2);
            s += __shfl_xor_sync(0xFFFFFFFFu, s, 4);
            if (i == 0u) out[e] = 1.0f / (1.0f + __expf(-s));
        }
    }
}

extern "C" void kernel_launch(void* const* d_in, const int* in_sizes, int n_in,
                              void* d_out, int out_size)
{
    const float* x  = (const float*)d_in[0];   // [N_NODES, 32]
    const float* R  = (const float*)d_in[1];   // [N_REL, 32]
    const int*   ei = (const int*)d_in[2];     // [2, E] int32
    const int*   et = (const int*)d_in[3];     // [E] int32
    float* out = (float*)d_out;

    int E = in_sizes[3];

    const int threads = 256;
    long long groups = ((long long)E + 3) / 4;
    long long total = groups * 8;
    int blocks = (int)((total + threads - 1) / threads);
    distmult_kernel<<<blocks, threads>>>(x, R, ei, et, out, E);
}

// round 7
// speedup vs baseline: 1.2461x; 1.2461x over previous
#include <cuda_runtime.h>
#include <cuda_bf16.h>
#include <cstdint>

// DistMult decoder: out[e] = sigmoid( sum_d x[l,d] * R[t,d] * x[r,d] )
// E = 4M edges, D = 32 floats (row = 128B = one L2 line).
//
// R6 lesson: forcing a 42-reg ceiling serialized the gather batch -> regression.
// Back to the R5 shape (48 regs, 5 blocks/SM). R7 change: the 64 scalar
// FFMA/FMUL per warp dominate issue; replace with packed f32x2 ops
// (sm_103a PTX-only: mul.rn.f32x2 / fma.rn.f32x2) -> 5 math ops/edge vs 8.

#define DIM 32

__device__ __forceinline__ unsigned long long pk2(float lo, float hi) {
    unsigned long long r;
    asm("mov.b64 %0, {%1, %2};" : "=l"(r) : "f"(lo), "f"(hi));
    return r;
}
__device__ __forceinline__ unsigned long long mul2(unsigned long long a, unsigned long long b) {
    unsigned long long r;
    asm("mul.rn.f32x2 %0, %1, %2;" : "=l"(r) : "l"(a), "l"(b));
    return r;
}
__device__ __forceinline__ unsigned long long fma2(unsigned long long a, unsigned long long b, unsigned long long c) {
    unsigned long long r;
    asm("fma.rn.f32x2 %0, %1, %2, %3;" : "=l"(r) : "l"(a), "l"(b), "l"(c));
    return r;
}
__device__ __forceinline__ float hadd2(unsigned long long v) {
    float lo, hi;
    asm("mov.b64 {%0, %1}, %2;" : "=f"(lo), "=f"(hi) : "l"(v));
    return lo + hi;
}

// score for one edge given packed relation halves
__device__ __forceinline__ float edge_score(const float4& a, const float4& b,
                                            unsigned long long cP0, unsigned long long cP1) {
    unsigned long long acc = mul2(mul2(pk2(a.x, a.y), cP0), pk2(b.x, b.y));
    acc = fma2(mul2(pk2(a.z, a.w), cP1), pk2(b.z, b.w), acc);
    return hadd2(acc);
}

__global__ void __launch_bounds__(256, 5) distmult_kernel(
    const float* __restrict__ x,
    const float* __restrict__ R,
    const int* __restrict__ edge_index,  // [2, E] int32
    const int* __restrict__ edge_type,   // [E] int32
    float* __restrict__ out,
    int E)
{
    int tid = blockIdx.x * blockDim.x + threadIdx.x;
    int g = tid >> 3;               // 8-lane group; handles edges 4g..4g+3
    unsigned i = threadIdx.x & 7u;  // 16B chunk within a row
    int e0 = g * 4;
    if (e0 >= E) return;

    const float4* __restrict__ xv = reinterpret_cast<const float4*>(x);
    const float4* __restrict__ rv = reinterpret_cast<const float4*>(R);

    if (e0 + 3 < E) {
        int4 L  = reinterpret_cast<const int4*>(edge_index)[g];
        int4 Rt = reinterpret_cast<const int4*>(edge_index + E)[g];
        int t0 = edge_type[e0];
        int t3 = edge_type[e0 + 3];

        // 8 independent coalesced 16B gathers (one 128B line per edge row)
        float4 a0 = xv[(unsigned)L.x * 8u + i];
        float4 a1 = xv[(unsigned)L.y * 8u + i];
        float4 a2 = xv[(unsigned)L.z * 8u + i];
        float4 a3 = xv[(unsigned)L.w * 8u + i];
        float4 b0 = xv[(unsigned)Rt.x * 8u + i];
        float4 b1 = xv[(unsigned)Rt.y * 8u + i];
        float4 b2 = xv[(unsigned)Rt.z * 8u + i];
        float4 b3 = xv[(unsigned)Rt.w * 8u + i];

        float s0, s1, s2, s3;
        if (t0 == t3) {
            // sorted types: one shared R row (~99.9% of groups)
            float4 c = rv[(unsigned)t0 * 8u + i];
            unsigned long long cP0 = pk2(c.x, c.y);
            unsigned long long cP1 = pk2(c.z, c.w);
            s0 = edge_score(a0, b0, cP0, cP1);
            s1 = edge_score(a1, b1, cP0, cP1);
            s2 = edge_score(a2, b2, cP0, cP1);
            s3 = edge_score(a3, b3, cP0, cP1);
        } else {
            // relation boundary inside the group (rare)
            int t1 = edge_type[e0 + 1];
            int t2 = edge_type[e0 + 2];
            float4 c0 = rv[(unsigned)t0 * 8u + i];
            float4 c1 = rv[(unsigned)t1 * 8u + i];
            float4 c2 = rv[(unsigned)t2 * 8u + i];
            float4 c3 = rv[(unsigned)t3 * 8u + i];
            s0 = edge_score(a0, b0, pk2(c0.x, c0.y), pk2(c0.z, c0.w));
            s1 = edge_score(a1, b1, pk2(c1.x, c1.y), pk2(c1.z, c1.w));
            s2 = edge_score(a2, b2, pk2(c2.x, c2.y), pk2(c2.z, c2.w));
            s3 = edge_score(a3, b3, pk2(c3.x, c3.y), pk2(c3.z, c3.w));
        }

        // packed 8-lane reduction of 4 values: 7 SHFLs total
        s0 += __shfl_xor_sync(0xFFFFFFFFu, s0, 4);
        s1 += __shfl_xor_sync(0xFFFFFFFFu, s1, 4);
        s2 += __shfl_xor_sync(0xFFFFFFFFu, s2, 4);
        s3 += __shfl_xor_sync(0xFFFFFFFFu, s3, 4);
        bool b2sel = (i & 2u) != 0u;
        float keep01 = b2sel ? s1 : s0;
        float send01 = b2sel ? s0 : s1;
        keep01 += __shfl_xor_sync(0xFFFFFFFFu, send01, 2);
        float keep23 = b2sel ? s3 : s2;
        float send23 = b2sel ? s2 : s3;
        keep23 += __shfl_xor_sync(0xFFFFFFFFu, send23, 2);
        bool b1sel = (i & 1u) != 0u;
        float keep = b1sel ? keep23 : keep01;
        float send = b1sel ? keep01 : keep23;
        keep += __shfl_xor_sync(0xFFFFFFFFu, send, 1);
        // lane i in 0..3 holds edge e0 + ((i&1)<<1 | (i>>1))

        if (i < 4u) {
            int j = (int)(((i & 1u) << 1) | (i >> 1));
            out[e0 + j] = 1.0f / (1.0f + __expf(-keep));
        }
    } else {
        // scalar tail (unused when E % 4 == 0, kept for safety)
        for (int e = e0; e < E; e++) {
            int l = edge_index[e];
            int r = edge_index[E + e];
            int t = edge_type[e];
            float4 a = xv[(unsigned)l * 8u + i];
            float4 b = xv[(unsigned)r * 8u + i];
            float4 c = rv[(unsigned)t * 8u + i];
            float s = a.x * c.x * b.x;
            s = fmaf(a.y * c.y, b.y, s);
            s = fmaf(a.z * c.z, b.z, s);
            s = fmaf(a.w * c.w, b.w, s);
            s += __shfl_xor_sync(0xFFFFFFFFu, s, 1);
            s += __shfl_xor_sync(0xFFFFFFFFu, s, 2);
            s += __shfl_xor_sync(0xFFFFFFFFu, s, 4);
            if (i == 0u) out[e] = 1.0f / (1.0f + __expf(-s));
        }
    }
}

extern "C" void kernel_launch(void* const* d_in, const int* in_sizes, int n_in,
                              void* d_out, int out_size)
{
    const float* x  = (const float*)d_in[0];   // [N_NODES, 32]
    const float* R  = (const float*)d_in[1];   // [N_REL, 32]
    const int*   ei = (const int*)d_in[2];     // [2, E] int32
    const int*   et = (const int*)d_in[3];     // [E] int32
    float* out = (float*)d_out;

    int E = in_sizes[3];

    const int threads = 256;
    long long groups = ((long long)E + 3) / 4;
    long long total = groups * 8;
    int blocks = (int)((total + threads - 1) / threads);
    distmult_kernel<<<blocks, threads>>>(x, R, ei, et, out, E);
}

// round 8
// speedup vs baseline: 1.2593x; 1.0106x over previous
#include <cuda_runtime.h>
#include <cuda_bf16.h>
#include <cstdint>

// DistMult decoder: out[e] = sigmoid( sum_d x[l,d] * R[t,d] * x[r,d] )
// E = 4M edges, D = 32 floats (row = 128B = one L2 line).
//
// R7 lesson: f32x2 math helped, but pk2() after float4 loads re-paid the win
// in MOV pairs. R8: load rows directly as ulonglong2 -> f32x2 operands are
// register pairs by construction, zero packing instructions.

#define DIM 32

__device__ __forceinline__ unsigned long long mul2(unsigned long long a, unsigned long long b) {
    unsigned long long r;
    asm("mul.rn.f32x2 %0, %1, %2;" : "=l"(r) : "l"(a), "l"(b));
    return r;
}
__device__ __forceinline__ unsigned long long fma2(unsigned long long a, unsigned long long b, unsigned long long c) {
    unsigned long long r;
    asm("fma.rn.f32x2 %0, %1, %2, %3;" : "=l"(r) : "l"(a), "l"(b), "l"(c));
    return r;
}
__device__ __forceinline__ float hadd2(unsigned long long v) {
    float lo, hi;
    asm("mov.b64 {%0, %1}, %2;" : "=f"(lo), "=f"(hi) : "l"(v));
    return lo + hi;
}

// score for one edge: rows held as two packed f32x2 each
__device__ __forceinline__ float edge_score(const ulonglong2& a, const ulonglong2& b,
                                            unsigned long long cP0, unsigned long long cP1) {
    unsigned long long acc = mul2(mul2(a.x, cP0), b.x);
    acc = fma2(mul2(a.y, cP1), b.y, acc);
    return hadd2(acc);
}

__global__ void __launch_bounds__(256, 5) distmult_kernel(
    const float* __restrict__ x,
    const float* __restrict__ R,
    const int* __restrict__ edge_index,  // [2, E] int32
    const int* __restrict__ edge_type,   // [E] int32
    float* __restrict__ out,
    int E)
{
    int tid = blockIdx.x * blockDim.x + threadIdx.x;
    int g = tid >> 3;               // 8-lane group; handles edges 4g..4g+3
    unsigned i = threadIdx.x & 7u;  // 16B chunk within a row
    int e0 = g * 4;
    if (e0 >= E) return;

    const ulonglong2* __restrict__ xv = reinterpret_cast<const ulonglong2*>(x);
    const ulonglong2* __restrict__ rv = reinterpret_cast<const ulonglong2*>(R);

    if (e0 + 3 < E) {
        int4 L  = reinterpret_cast<const int4*>(edge_index)[g];
        int4 Rt = reinterpret_cast<const int4*>(edge_index + E)[g];
        int t0 = edge_type[e0];
        int t3 = edge_type[e0 + 3];

        // 8 independent coalesced 16B gathers (one 128B line per edge row)
        ulonglong2 a0 = xv[(unsigned)L.x * 8u + i];
        ulonglong2 a1 = xv[(unsigned)L.y * 8u + i];
        ulonglong2 a2 = xv[(unsigned)L.z * 8u + i];
        ulonglong2 a3 = xv[(unsigned)L.w * 8u + i];
        ulonglong2 b0 = xv[(unsigned)Rt.x * 8u + i];
        ulonglong2 b1 = xv[(unsigned)Rt.y * 8u + i];
        ulonglong2 b2 = xv[(unsigned)Rt.z * 8u + i];
        ulonglong2 b3 = xv[(unsigned)Rt.w * 8u + i];

        float s0, s1, s2, s3;
        if (t0 == t3) {
            // sorted types: one shared R row (~99.9% of groups)
            ulonglong2 c = rv[(unsigned)t0 * 8u + i];
            s0 = edge_score(a0, b0, c.x, c.y);
            s1 = edge_score(a1, b1, c.x, c.y);
            s2 = edge_score(a2, b2, c.x, c.y);
            s3 = edge_score(a3, b3, c.x, c.y);
        } else {
            // relation boundary inside the group (rare)
            int t1 = edge_type[e0 + 1];
            int t2 = edge_type[e0 + 2];
            ulonglong2 c0 = rv[(unsigned)t0 * 8u + i];
            ulonglong2 c1 = rv[(unsigned)t1 * 8u + i];
            ulonglong2 c2 = rv[(unsigned)t2 * 8u + i];
            ulonglong2 c3 = rv[(unsigned)t3 * 8u + i];
            s0 = edge_score(a0, b0, c0.x, c0.y);
            s1 = edge_score(a1, b1, c1.x, c1.y);
            s2 = edge_score(a2, b2, c2.x, c2.y);
            s3 = edge_score(a3, b3, c3.x, c3.y);
        }

        // packed 8-lane reduction of 4 values: 7 SHFLs total
        s0 += __shfl_xor_sync(0xFFFFFFFFu, s0, 4);
        s1 += __shfl_xor_sync(0xFFFFFFFFu, s1, 4);
        s2 += __shfl_xor_sync(0xFFFFFFFFu, s2, 4);
        s3 += __shfl_xor_sync(0xFFFFFFFFu, s3, 4);
        bool b2sel = (i & 2u) != 0u;
        float keep01 = b2sel ? s1 : s0;
        float send01 = b2sel ? s0 : s1;
        keep01 += __shfl_xor_sync(0xFFFFFFFFu, send01, 2);
        float keep23 = b2sel ? s3 : s2;
        float send23 = b2sel ? s2 : s3;
        keep23 += __shfl_xor_sync(0xFFFFFFFFu, send23, 2);
        bool b1sel = (i & 1u) != 0u;
        float keep = b1sel ? keep23 : keep01;
        float send = b1sel ? keep01 : keep23;
        keep += __shfl_xor_sync(0xFFFFFFFFu, send, 1);
        // lane i in 0..3 holds edge e0 + ((i&1)<<1 | (i>>1))

        if (i < 4u) {
            int j = (int)(((i & 1u) << 1) | (i >> 1));
            out[e0 + j] = 1.0f / (1.0f + __expf(-keep));
        }
    } else {
        // scalar tail (unused when E % 4 == 0, kept for safety)
        const float4* __restrict__ xf = reinterpret_cast<const float4*>(x);
        const float4* __restrict__ rf = reinterpret_cast<const float4*>(R);
        for (int e = e0; e < E; e++) {
            int l = edge_index[e];
            int r = edge_index[E + e];
            int t = edge_type[e];
            float4 a = xf[(unsigned)l * 8u + i];
            float4 b = xf[(unsigned)r * 8u + i];
            float4 c = rf[(unsigned)t * 8u + i];
            float s = a.x * c.x * b.x;
            s = fmaf(a.y * c.y, b.y, s);
            s = fmaf(a.z * c.z, b.z, s);
            s = fmaf(a.w * c.w, b.w, s);
            s += __shfl_xor_sync(0xFFFFFFFFu, s, 1);
            s += __shfl_xor_sync(0xFFFFFFFFu, s, 2);
            s += __shfl_xor_sync(0xFFFFFFFFu, s, 4);
            if (i == 0u) out[e] = 1.0f / (1.0f + __expf(-s));
        }
    }
}

extern "C" void kernel_launch(void* const* d_in, const int* in_sizes, int n_in,
                              void* d_out, int out_size)
{
    const float* x  = (const float*)d_in[0];   // [N_NODES, 32]
    const float* R  = (const float*)d_in[1];   // [N_REL, 32]
    const int*   ei = (const int*)d_in[2];     // [2, E] int32
    const int*   et = (const int*)d_in[3];     // [E] int32
    float* out = (float*)d_out;

    int E = in_sizes[3];

    const int threads = 256;
    long long groups = ((long long)E + 3) / 4;
    long long total = groups * 8;
    int blocks = (int)((total + threads - 1) / threads);
    distmult_kernel<<<blocks, threads>>>(x, R, ei, et, out, E);
}

// round 9
// speedup vs baseline: 1.3012x; 1.0333x over previous
#include <cuda_runtime.h>
#include <cuda_bf16.h>
#include <cstdint>

// DistMult decoder: out[e] = sigmoid( sum_d x[l,d] * R[t,d] * x[r,d] )
// E = 4M edges, D = 32 floats (row = 128B = one L2 line).
//
// R8 state: 63.6us, latency-bound (L1 64%, L2 61%, issue 38%, occ 54%).
// R9: raise in-flight bytes/SM. 8 edges per 8-lane group -> 16 independent
// row gathers per thread; launch_bounds(256,3) (85-reg ceiling, 24 warps/SM).
// Net in-flight loads/SM +37%. Fully-coalesced 8-lane output store.

#define DIM 32

__device__ __forceinline__ unsigned long long mul2(unsigned long long a, unsigned long long b) {
    unsigned long long r;
    asm("mul.rn.f32x2 %0, %1, %2;" : "=l"(r) : "l"(a), "l"(b));
    return r;
}
__device__ __forceinline__ unsigned long long fma2(unsigned long long a, unsigned long long b, unsigned long long c) {
    unsigned long long r;
    asm("fma.rn.f32x2 %0, %1, %2, %3;" : "=l"(r) : "l"(a), "l"(b), "l"(c));
    return r;
}
__device__ __forceinline__ float hadd2(unsigned long long v) {
    float lo, hi;
    asm("mov.b64 {%0, %1}, %2;" : "=f"(lo), "=f"(hi) : "l"(v));
    return lo + hi;
}

__device__ __forceinline__ float edge_score(const ulonglong2& a, const ulonglong2& b,
                                            unsigned long long cP0, unsigned long long cP1) {
    unsigned long long acc = mul2(mul2(a.x, cP0), b.x);
    acc = fma2(mul2(a.y, cP1), b.y, acc);
    return hadd2(acc);
}

__global__ void __launch_bounds__(256, 3) distmult_kernel(
    const float* __restrict__ x,
    const float* __restrict__ R,
    const int* __restrict__ edge_index,  // [2, E] int32
    const int* __restrict__ edge_type,   // [E] int32
    float* __restrict__ out,
    int E)
{
    int tid = blockIdx.x * blockDim.x + threadIdx.x;
    int g = tid >> 3;               // 8-lane group; handles edges 8g..8g+7
    unsigned i = threadIdx.x & 7u;  // 16B chunk within a row
    int e0 = g * 8;
    if (e0 >= E) return;

    const ulonglong2* __restrict__ xv = reinterpret_cast<const ulonglong2*>(x);
    const ulonglong2* __restrict__ rv = reinterpret_cast<const ulonglong2*>(R);

    if (e0 + 7 < E) {
        const int4* Lp = reinterpret_cast<const int4*>(edge_index);
        const int4* Rp = reinterpret_cast<const int4*>(edge_index + E);
        int4 La = Lp[2 * g];
        int4 Lb = Lp[2 * g + 1];
        int4 Ra = Rp[2 * g];
        int4 Rb = Rp[2 * g + 1];
        int t0 = edge_type[e0];
        int t7 = edge_type[e0 + 7];

        // 16 independent coalesced 16B gathers (one 128B line per edge row)
        ulonglong2 a0 = xv[(unsigned)La.x * 8u + i];
        ulonglong2 a1 = xv[(unsigned)La.y * 8u + i];
        ulonglong2 a2 = xv[(unsigned)La.z * 8u + i];
        ulonglong2 a3 = xv[(unsigned)La.w * 8u + i];
        ulonglong2 a4 = xv[(unsigned)Lb.x * 8u + i];
        ulonglong2 a5 = xv[(unsigned)Lb.y * 8u + i];
        ulonglong2 a6 = xv[(unsigned)Lb.z * 8u + i];
        ulonglong2 a7 = xv[(unsigned)Lb.w * 8u + i];
        ulonglong2 b0 = xv[(unsigned)Ra.x * 8u + i];
        ulonglong2 b1 = xv[(unsigned)Ra.y * 8u + i];
        ulonglong2 b2 = xv[(unsigned)Ra.z * 8u + i];
        ulonglong2 b3 = xv[(unsigned)Ra.w * 8u + i];
        ulonglong2 b4 = xv[(unsigned)Rb.x * 8u + i];
        ulonglong2 b5 = xv[(unsigned)Rb.y * 8u + i];
        ulonglong2 b6 = xv[(unsigned)Rb.z * 8u + i];
        ulonglong2 b7 = xv[(unsigned)Rb.w * 8u + i];

        float s0, s1, s2, s3, s4, s5, s6, s7;
        if (t0 == t7) {
            // sorted types: one shared R row (~99.8% of groups)
            ulonglong2 c = rv[(unsigned)t0 * 8u + i];
            s0 = edge_score(a0, b0, c.x, c.y);
            s1 = edge_score(a1, b1, c.x, c.y);
            s2 = edge_score(a2, b2, c.x, c.y);
            s3 = edge_score(a3, b3, c.x, c.y);
            s4 = edge_score(a4, b4, c.x, c.y);
            s5 = edge_score(a5, b5, c.x, c.y);
            s6 = edge_score(a6, b6, c.x, c.y);
            s7 = edge_score(a7, b7, c.x, c.y);
        } else {
            // relation boundary inside the group (rare)
            ulonglong2 c;
            c = rv[(unsigned)edge_type[e0 + 0] * 8u + i]; s0 = edge_score(a0, b0, c.x, c.y);
            c = rv[(unsigned)edge_type[e0 + 1] * 8u + i]; s1 = edge_score(a1, b1, c.x, c.y);
            c = rv[(unsigned)edge_type[e0 + 2] * 8u + i]; s2 = edge_score(a2, b2, c.x, c.y);
            c = rv[(unsigned)edge_type[e0 + 3] * 8u + i]; s3 = edge_score(a3, b3, c.x, c.y);
            c = rv[(unsigned)edge_type[e0 + 4] * 8u + i]; s4 = edge_score(a4, b4, c.x, c.y);
            c = rv[(unsigned)edge_type[e0 + 5] * 8u + i]; s5 = edge_score(a5, b5, c.x, c.y);
            c = rv[(unsigned)edge_type[e0 + 6] * 8u + i]; s6 = edge_score(a6, b6, c.x, c.y);
            c = rv[(unsigned)t7 * 8u + i];                s7 = edge_score(a7, b7, c.x, c.y);
        }

        // packed 8-lane reduction of 8 values: 14 SHFLs
        s0 += __shfl_xor_sync(0xFFFFFFFFu, s0, 4);
        s1 += __shfl_xor_sync(0xFFFFFFFFu, s1, 4);
        s2 += __shfl_xor_sync(0xFFFFFFFFu, s2, 4);
        s3 += __shfl_xor_sync(0xFFFFFFFFu, s3, 4);
        s4 += __shfl_xor_sync(0xFFFFFFFFu, s4, 4);
        s5 += __shfl_xor_sync(0xFFFFFFFFu, s5, 4);
        s6 += __shfl_xor_sync(0xFFFFFFFFu, s6, 4);
        s7 += __shfl_xor_sync(0xFFFFFFFFu, s7, 4);

        bool b2sel = (i & 2u) != 0u;
        float u0k = b2sel ? s1 : s0, u0s = b2sel ? s0 : s1;
        u0k += __shfl_xor_sync(0xFFFFFFFFu, u0s, 2);
        float u1k = b2sel ? s3 : s2, u1s = b2sel ? s2 : s3;
        u1k += __shfl_xor_sync(0xFFFFFFFFu, u1s, 2);
        float u2k = b2sel ? s5 : s4, u2s = b2sel ? s4 : s5;
        u2k += __shfl_xor_sync(0xFFFFFFFFu, u2s, 2);
        float u3k = b2sel ? s7 : s6, u3s = b2sel ? s6 : s7;
        u3k += __shfl_xor_sync(0xFFFFFFFFu, u3s, 2);

        bool b1sel = (i & 1u) != 0u;
        float w0 = b1sel ? u1k : u0k, w0s = b1sel ? u0k : u1k;
        w0 += __shfl_xor_sync(0xFFFFFFFFu, w0s, 1);
        float w1 = b1sel ? u3k : u2k, w1s = b1sel ? u2k : u3k;
        w1 += __shfl_xor_sync(0xFFFFFFFFu, w1s, 1);
        // lanes 0-3: w0 = edges {0,2,1,3}; lanes 4-7 duplicate, use w1 = edges {4,6,5,7}

        unsigned low = i & 3u;
        int j = (int)(((low & 1u) << 1) | (low >> 1)) + (i >= 4u ? 4 : 0);
        float val = (i >= 4u) ? w1 : w0;
        out[e0 + j] = 1.0f / (1.0f + __expf(-val));  // 8 consecutive floats per group
    } else {
        // scalar tail (unused when E % 8 == 0, kept for safety)
        const float4* __restrict__ xf = reinterpret_cast<const float4*>(x);
        const float4* __restrict__ rf = reinterpret_cast<const float4*>(R);
        for (int e = e0; e < E; e++) {
            int l = edge_index[e];
            int r = edge_index[E + e];
            int t = edge_type[e];
            float4 a = xf[(unsigned)l * 8u + i];
            float4 b = xf[(unsigned)r * 8u + i];
            float4 c = rf[(unsigned)t * 8u + i];
            float s = a.x * c.x * b.x;
            s = fmaf(a.y * c.y, b.y, s);
            s = fmaf(a.z * c.z, b.z, s);
            s = fmaf(a.w * c.w, b.w, s);
            s += __shfl_xor_sync(0xFFFFFFFFu, s, 1);
            s += __shfl_xor_sync(0xFFFFFFFFu, s, 2);
            s += __shfl_xor_sync(0xFFFFFFFFu, s, 4);
            if (i == 0u) out[e] = 1.0f / (1.0f + __expf(-s));
        }
    }
}

extern "C" void kernel_launch(void* const* d_in, const int* in_sizes, int n_in,
                              void* d_out, int out_size)
{
    const float* x  = (const float*)d_in[0];   // [N_NODES, 32]
    const float* R  = (const float*)d_in[1];   // [N_REL, 32]
    const int*   ei = (const int*)d_in[2];     // [2, E] int32
    const int*   et = (const int*)d_in[3];     // [E] int32
    float* out = (float*)d_out;

    int E = in_sizes[3];

    const int threads = 256;
    long long groups = ((long long)E + 7) / 8;   // 8 edges per 8-lane group
    long long total = groups * 8;
    int blocks = (int)((total + threads - 1) / threads);
    distmult_kernel<<<blocks, threads>>>(x, R, ei, et, out, E);
}